// round 14
// baseline (speedup 1.0000x reference)
#include <cuda_runtime.h>
#include <cuda_bf16.h>
#include <cstdint>

#define EMB 1024
#define HEADS 16
#define HDIM 64
#define BATCH 2
#define SEQ 2048
#define MTOT (BATCH*SEQ)
#define ATT_SCALE 0.125f

// ---------------------------------------------------------------------------
// Device-global scratch (no allocations allowed)
// ---------------------------------------------------------------------------
#define QKV_ELEMS ((size_t)BATCH*HEADS*SEQ*HDIM)
__device__ __align__(256) __nv_bfloat16 g_xh[(size_t)MTOT*EMB];
__device__ __align__(256) __nv_bfloat16 g_xl[(size_t)MTOT*EMB];
__device__ __align__(256) __nv_bfloat16 g_wqh[(size_t)3*EMB*EMB];
__device__ __align__(256) __nv_bfloat16 g_wql[(size_t)3*EMB*EMB];
__device__ __align__(256) __nv_bfloat16 g_wph[(size_t)EMB*EMB];
__device__ __align__(256) __nv_bfloat16 g_wpl[(size_t)EMB*EMB];
__device__ __align__(256) __nv_bfloat16 g_qh[QKV_ELEMS];
__device__ __align__(256) __nv_bfloat16 g_ql[QKV_ELEMS];
__device__ __align__(256) __nv_bfloat16 g_kh[QKV_ELEMS];
__device__ __align__(256) __nv_bfloat16 g_kl[QKV_ELEMS];
__device__ __align__(256) __nv_bfloat16 g_vh[QKV_ELEMS];
__device__ __align__(256) __nv_bfloat16 g_vl[QKV_ELEMS];
__device__ __align__(256) __nv_bfloat16 g_ah[(size_t)MTOT*EMB];
__device__ __align__(256) __nv_bfloat16 g_al[(size_t)MTOT*EMB];

// ---------------------------------------------------------------------------
// Low-level helpers (all plain sm_80+ PTX — compiles at compute_103)
// ---------------------------------------------------------------------------
__device__ __forceinline__ uint32_t smem_u32(const void* p) {
    uint32_t a;
    asm("{ .reg .u64 t; cvta.to.shared.u64 t, %1; cvt.u32.u64 %0, t; }"
        : "=r"(a) : "l"(p));
    return a;
}
__device__ __forceinline__ void ldsm_x4(uint32_t r[4], uint32_t addr) {
    asm volatile("ldmatrix.sync.aligned.m8n8.x4.shared.b16 {%0,%1,%2,%3}, [%4];"
        : "=r"(r[0]), "=r"(r[1]), "=r"(r[2]), "=r"(r[3]) : "r"(addr));
}
__device__ __forceinline__ void ldsm_x4_t(uint32_t r[4], uint32_t addr) {
    asm volatile("ldmatrix.sync.aligned.m8n8.x4.trans.shared.b16 {%0,%1,%2,%3}, [%4];"
        : "=r"(r[0]), "=r"(r[1]), "=r"(r[2]), "=r"(r[3]) : "r"(addr));
}
__device__ __forceinline__ void mma_bf16(float c[4], const uint32_t a[4],
                                         uint32_t b0, uint32_t b1) {
    asm volatile("mma.sync.aligned.m16n8k16.row.col.f32.bf16.bf16.f32 "
        "{%0,%1,%2,%3}, {%4,%5,%6,%7}, {%8,%9}, {%0,%1,%2,%3};"
        : "+f"(c[0]), "+f"(c[1]), "+f"(c[2]), "+f"(c[3])
        : "r"(a[0]), "r"(a[1]), "r"(a[2]), "r"(a[3]), "r"(b0), "r"(b1));
}
#define CP_ASYNC16(sptr, gptr) \
    asm volatile("cp.async.cg.shared.global [%0], [%1], 16;" \
                 :: "r"(sptr), "l"(gptr) : "memory")
#define CP_COMMIT()  asm volatile("cp.async.commit_group;" ::: "memory")
#define CP_WAIT0()   asm volatile("cp.async.wait_group 0;" ::: "memory")
#define CP_WAIT1()   asm volatile("cp.async.wait_group 1;" ::: "memory")

// XOR swizzle within 1KB (8 rows x 128B): chunk index ^= row%8
#define SWZ(off) ((off) ^ (((off) >> 3) & 0x70))

__device__ __forceinline__ float truncbf(float x) {
    return __uint_as_float(__float_as_uint(x) & 0xffff0000u);
}
// pack two f32 into bf16x2 (lo = e0 in low half)
__device__ __forceinline__ uint32_t pack_bf16x2(float lo, float hi) {
    uint32_t r;
    asm("cvt.rn.satfinite.bf16x2.f32 %0, %1, %2;" : "=r"(r) : "f"(hi), "f"(lo));
    return r;
}
__device__ __forceinline__ void split_pair(float e0, float e1,
                                           uint32_t& hp, uint32_t& lp) {
    float h0 = truncbf(e0), h1 = truncbf(e1);
    hp = pack_bf16x2(h0, h1);
    lp = pack_bf16x2(e0 - h0, e1 - h1);
}

// ---------------------------------------------------------------------------
// Split fp32 -> (hi, lo) bf16
// ---------------------------------------------------------------------------
__global__ void convert_split_kernel(const float* __restrict__ in,
                                     __nv_bfloat16* __restrict__ hi,
                                     __nv_bfloat16* __restrict__ lo, int n)
{
    int i = blockIdx.x * blockDim.x + threadIdx.x;
    if (i < n) {
        float x = in[i];
        float h = truncbf(x);
        hi[i] = __float2bfloat16(h);
        lo[i] = __float2bfloat16(x - h);
    }
}

// ---------------------------------------------------------------------------
// Transpose + split: W[1024][N] fp32 -> WT[N][1024] bf16 hi/lo
// ---------------------------------------------------------------------------
__global__ void transpose_split_kernel(const float* __restrict__ W, int N,
                                       __nv_bfloat16* __restrict__ Th,
                                       __nv_bfloat16* __restrict__ Tl)
{
    __shared__ float tile[32][33];
    int n0 = blockIdx.x * 32, k0 = blockIdx.y * 32;
    int tx = threadIdx.x, ty = threadIdx.y;
#pragma unroll
    for (int i = 0; i < 32; i += 8)
        tile[ty + i][tx] = W[(size_t)(k0 + ty + i) * N + n0 + tx];
    __syncthreads();
#pragma unroll
    for (int i = 0; i < 32; i += 8) {
        float v = tile[tx][ty + i];
        float h = truncbf(v);
        size_t idx = (size_t)(n0 + ty + i) * EMB + k0 + tx;
        Th[idx] = __float2bfloat16(h);
        Tl[idx] = __float2bfloat16(v - h);
    }
}

// ---------------------------------------------------------------------------
// HMMA bf16x3 GEMM: C[4096][Ntot] = A[4096][1024] @ B^T  (B stored [N][1024])
// CTA tile 128x128, 16 warps (4 M x 4 N), warp tile 32x32, K-chunk 64,
// 128B swizzled smem rows, double-buffered cp.async stages.
// R13: register double-buffered fragments — issue ks+1's ldmatrix batch
// BEFORE ks's MMAs so the smem crossbar and tensor pipe overlap per-warp
// (R12 profile showed the pipes serializing in barrier-phase convoy).
// mode 0: QKV epilogue (bias + de-interleave + bf16 hi/lo scatter)
// mode 1: bias + fp32 write to outp.
// ---------------------------------------------------------------------------
#define GKC 64
#define GNCH (EMB/GKC)          // 16
#define GROWB 128               // 64 bf16 = 128B per row, swizzled
#define GARR (128*GROWB)        // 16384
#define GSTAGE (4*GARR)         // 65536
#define GEMM_SMEM (2*GSTAGE)    // 131072

__device__ __forceinline__ void qkv_scatter(int r, int c, float val,
                                            const float* __restrict__ bias)
{
    val += bias[c];
    int bb = r >> 11;
    int n  = r & (SEQ - 1);
    int h   = c / 192;
    int rem = c - h * 192;
    int d   = rem / 3;
    int w   = rem - d * 3;
    size_t idx = (((size_t)(bb * HEADS + h)) * SEQ + n) * HDIM + d;
    float hi = truncbf(val);
    float lo = val - hi;
    __nv_bfloat16* dh = (w == 0) ? g_qh : (w == 1) ? g_kh : g_vh;
    __nv_bfloat16* dl = (w == 0) ? g_ql : (w == 1) ? g_kl : g_vl;
    dh[idx] = __float2bfloat16(hi);
    dl[idx] = __float2bfloat16(lo);
}

__global__ __launch_bounds__(512, 1)
void mma_gemm_kernel(const __nv_bfloat16* __restrict__ Ah,
                     const __nv_bfloat16* __restrict__ Al,
                     const __nv_bfloat16* __restrict__ Bh,
                     const __nv_bfloat16* __restrict__ Bl,
                     const float* __restrict__ bias,
                     float* __restrict__ outp, int mode)
{
    extern __shared__ char smem[];
    const uint32_t sbase = smem_u32(smem);
    const int tid = threadIdx.x, lane = tid & 31, wid = tid >> 5;
    const int wm = (wid >> 2) * 32, wn = (wid & 3) * 32;
    const int mBase = blockIdx.y * 128, nBase = blockIdx.x * 128;

    const int arow = wm + (lane & 15);
    const int acolb = (lane >> 4) * 16;
    const int brow = wn + ((lane >> 4) << 3) + (lane & 7);
    const int bcolb = ((lane >> 3) & 1) * 16;

    float acc[2][4][4];
#pragma unroll
    for (int a = 0; a < 2; a++)
#pragma unroll
        for (int b = 0; b < 4; b++)
#pragma unroll
            for (int e = 0; e < 4; e++) acc[a][b][e] = 0.f;

    // double-buffered fragment registers
    uint32_t ah4[2][2][4], al4[2][2][4], bh4[2][2][4], bl4[2][2][4];

    // stage loader: 4 arrays x 128 rows x 8 x 16B chunks = 4096 tasks / 512 thr
    auto load_stage = [&](int t, int st) {
        const int k0 = t * GKC;
        const __nv_bfloat16* arrs[4] = {Ah, Al, Bh, Bl};
#pragma unroll
        for (int i = 0; i < 8; i++) {
            int task = i * 512 + tid;
            int arr = task >> 10, rem = task & 1023;
            int row = rem >> 3, ch = rem & 7;
            const __nv_bfloat16* g = arrs[arr];
            const int rb = (arr < 2) ? mBase : nBase;
            const uint32_t ab = sbase + st * GSTAGE + arr * GARR;
            const void* gp = g + (size_t)(rb + row) * EMB + k0 + ch * 8;
            CP_ASYNC16(ab + SWZ(row * GROWB + ch * 16), gp);
        }
    };

    load_stage(0, 0); CP_COMMIT();

    for (int t = 0; t < GNCH; t++) {
        const int st = t & 1;
        if (t + 1 < GNCH) { load_stage(t + 1, st ^ 1); CP_COMMIT(); CP_WAIT1(); }
        else              { CP_WAIT0(); }
        __syncthreads();

        const uint32_t aH = sbase + st * GSTAGE;
        const uint32_t aL = aH + GARR, bH = aH + 2 * GARR, bL = aH + 3 * GARR;

        // fragment loader for this chunk's k-step ks into buffer f
        auto load_frags = [&](int ks, int f) {
            const int acol = ks * 32 + acolb;
#pragma unroll
            for (int mt = 0; mt < 2; mt++) {
                ldsm_x4(ah4[f][mt], aH + SWZ((arow + mt * 16) * GROWB + acol));
                ldsm_x4(al4[f][mt], aL + SWZ((arow + mt * 16) * GROWB + acol));
            }
            const int bcol = ks * 32 + bcolb;
#pragma unroll
            for (int np = 0; np < 2; np++) {
                ldsm_x4(bh4[f][np], bH + SWZ((brow + np * 16) * GROWB + bcol));
                ldsm_x4(bl4[f][np], bL + SWZ((brow + np * 16) * GROWB + bcol));
            }
        };

        load_frags(0, 0);
#pragma unroll
        for (int ks = 0; ks < 4; ks++) {
            const int cur = ks & 1;
            if (ks < 3) load_frags(ks + 1, cur ^ 1);   // prefetch next k-step
#pragma unroll
            for (int mt = 0; mt < 2; mt++)
#pragma unroll
                for (int nt = 0; nt < 4; nt++) {
                    uint32_t b0h = bh4[cur][nt >> 1][(nt & 1) * 2];
                    uint32_t b1h = bh4[cur][nt >> 1][(nt & 1) * 2 + 1];
                    uint32_t b0l = bl4[cur][nt >> 1][(nt & 1) * 2];
                    uint32_t b1l = bl4[cur][nt >> 1][(nt & 1) * 2 + 1];
                    mma_bf16(acc[mt][nt], ah4[cur][mt], b0h, b1h);
                    mma_bf16(acc[mt][nt], ah4[cur][mt], b0l, b1l);
                    mma_bf16(acc[mt][nt], al4[cur][mt], b0h, b1h);
                }
        }
        __syncthreads();
    }

    // epilogue
#pragma unroll
    for (int mt = 0; mt < 2; mt++) {
        const int r0 = mBase + wm + mt * 16 + (lane >> 2);
#pragma unroll
        for (int nt = 0; nt < 4; nt++) {
            const int c0 = nBase + wn + nt * 8 + 2 * (lane & 3);
            if (mode == 0) {
                qkv_scatter(r0,     c0,     acc[mt][nt][0], bias);
                qkv_scatter(r0,     c0 + 1, acc[mt][nt][1], bias);
                qkv_scatter(r0 + 8, c0,     acc[mt][nt][2], bias);
                qkv_scatter(r0 + 8, c0 + 1, acc[mt][nt][3], bias);
            } else {
                float2 v0 = {acc[mt][nt][0] + bias[c0], acc[mt][nt][1] + bias[c0 + 1]};
                float2 v1 = {acc[mt][nt][2] + bias[c0], acc[mt][nt][3] + bias[c0 + 1]};
                *(float2*)(outp + (size_t)r0 * EMB + c0) = v0;
                *(float2*)(outp + (size_t)(r0 + 8) * EMB + c0) = v1;
            }
        }
    }
}

// ---------------------------------------------------------------------------
// Flash attention on HMMA bf16 hi/lo (unchanged this round — isolating the
// GEMM schedule change). Block = 64 q-rows of one (b,h), 4 warps, 64-key
// tiles, double-buffered K/V cp.async. Rows are 64 bf16 = 128B = 8 chunks.
// S = Qh.Kh + Qh.Kl + Ql.Kh; online softmax in regs; P repacked register-only;
// O += Ph.Vh + Ph.Vl + Pl.Vh (V via ldmatrix.trans). softmax THEN scale.
// Output -> g_ah/g_al bf16 hi/lo at [b][n][h*64+d].
// ---------------------------------------------------------------------------
#define FROWB 144                       // 64 bf16 = 128B data + 16B pad
#define FARR (64*FROWB)                 // 9216
#define FKV_BASE (2*FARR)               // after Qh,Ql
#define FSTAGE (4*FARR)                 // Kh,Kl,Vh,Vl
#define FLASH_SMEM (FKV_BASE + 2*FSTAGE) // 92160

__global__ __launch_bounds__(128, 2)
void flash_kernel()
{
    extern __shared__ char smem[];
    const uint32_t sbase = smem_u32(smem);
    const int tid = threadIdx.x, lane = tid & 31, w = tid >> 5;
    const int bh = blockIdx.y, qt = blockIdx.x;
    const int bb = bh >> 4, h = bh & 15;
    const size_t hoff = (size_t)bh * SEQ * HDIM;

    // --- load Q tile (hi/lo): 2 arrays x 64 rows x 8 chunks = 1024 tasks ---
    {
        const __nv_bfloat16* qa[2] = {g_qh + hoff, g_ql + hoff};
#pragma unroll
        for (int i = 0; i < 8; i++) {
            int task = i * 128 + tid;
            int arr = task >> 9, rem = task & 511;
            int row = rem >> 3, ch = rem & 7;
            const void* gp = qa[arr] + (size_t)(qt * 64 + row) * HDIM + ch * 8;
            CP_ASYNC16(sbase + arr * FARR + row * FROWB + ch * 16, gp);
        }
    }
    CP_COMMIT();

    // 4 arrays x 64 rows x 8 chunks = 2048 tasks
    auto load_kv = [&](int kt, int st) {
        const __nv_bfloat16* ka[4] = {g_kh + hoff, g_kl + hoff,
                                      g_vh + hoff, g_vl + hoff};
        const uint32_t kb = sbase + FKV_BASE + st * FSTAGE;
#pragma unroll
        for (int i = 0; i < 16; i++) {
            int task = i * 128 + tid;
            int arr = task >> 9, rem = task & 511;
            int row = rem >> 3, ch = rem & 7;
            const void* gp = ka[arr] + (size_t)(kt * 64 + row) * HDIM + ch * 8;
            CP_ASYNC16(kb + arr * FARR + row * FROWB + ch * 16, gp);
        }
    };

    load_kv(0, 0); CP_COMMIT();
    CP_WAIT1();               // Q group done
    __syncthreads();

    // --- Q fragments (persistent): 4 k-steps x 4 regs, hi & lo ---
    uint32_t aqh[4][4], aql[4][4];
    {
        const int arow = 16 * w + (lane & 15);
        const int acolb = (lane >> 4) * 16;
#pragma unroll
        for (int ks = 0; ks < 4; ks++) {
            ldsm_x4(aqh[ks], sbase + arow * FROWB + ks * 32 + acolb);
            ldsm_x4(aql[ks], sbase + FARR + arow * FROWB + ks * 32 + acolb);
        }
    }

    float o[8][4];
#pragma unroll
    for (int dt = 0; dt < 8; dt++)
#pragma unroll
        for (int e = 0; e < 4; e++) o[dt][e] = 0.f;
    float m0 = -1e30f, m1 = -1e30f, l0 = 0.f, l1 = 0.f;

    for (int kt = 0; kt < SEQ / 64; kt++) {
        const int st = kt & 1;
        if (kt + 1 < SEQ / 64) { load_kv(kt + 1, st ^ 1); CP_COMMIT(); CP_WAIT1(); }
        else                   { CP_WAIT0(); }
        __syncthreads();

        const uint32_t kH = sbase + FKV_BASE + st * FSTAGE;
        const uint32_t kL = kH + FARR, vH = kH + 2 * FARR, vL = kH + 3 * FARR;

        // ---- S = Q K^T (3-pass) ----
        float s[8][4];
#pragma unroll
        for (int nt = 0; nt < 8; nt++)
#pragma unroll
            for (int e = 0; e < 4; e++) s[nt][e] = 0.f;

        {
            const int brow = ((lane >> 4) << 3) + (lane & 7);
            const int bcolb = ((lane >> 3) & 1) * 16;
#pragma unroll
            for (int ks = 0; ks < 4; ks++) {
                uint32_t bh4[4][4], bl4[4][4];
#pragma unroll
                for (int np = 0; np < 4; np++) {
                    ldsm_x4(bh4[np], kH + (np * 16 + brow) * FROWB + ks * 32 + bcolb);
                    ldsm_x4(bl4[np], kL + (np * 16 + brow) * FROWB + ks * 32 + bcolb);
                }
#pragma unroll
                for (int nt = 0; nt < 8; nt++) {
                    uint32_t b0h = bh4[nt >> 1][(nt & 1) * 2];
                    uint32_t b1h = bh4[nt >> 1][(nt & 1) * 2 + 1];
                    uint32_t b0l = bl4[nt >> 1][(nt & 1) * 2];
                    uint32_t b1l = bl4[nt >> 1][(nt & 1) * 2 + 1];
                    mma_bf16(s[nt], aqh[ks], b0h, b1h);
                    mma_bf16(s[nt], aqh[ks], b0l, b1l);
                    mma_bf16(s[nt], aql[ks], b0h, b1h);
                }
            }
        }

        // ---- online softmax (rows m=lane/4 and m+8; reduce over lane%4) ----
        float vx0 = -1e30f, vx1 = -1e30f;
#pragma unroll
        for (int nt = 0; nt < 8; nt++) {
            vx0 = fmaxf(vx0, fmaxf(s[nt][0], s[nt][1]));
            vx1 = fmaxf(vx1, fmaxf(s[nt][2], s[nt][3]));
        }
        vx0 = fmaxf(vx0, __shfl_xor_sync(0xffffffffu, vx0, 1));
        vx0 = fmaxf(vx0, __shfl_xor_sync(0xffffffffu, vx0, 2));
        vx1 = fmaxf(vx1, __shfl_xor_sync(0xffffffffu, vx1, 1));
        vx1 = fmaxf(vx1, __shfl_xor_sync(0xffffffffu, vx1, 2));
        const float mn0 = fmaxf(m0, vx0), mn1 = fmaxf(m1, vx1);
        const float cr0 = __expf(m0 - mn0), cr1 = __expf(m1 - mn1);
        float sum0 = 0.f, sum1 = 0.f;
#pragma unroll
        for (int nt = 0; nt < 8; nt++) {
            s[nt][0] = __expf(s[nt][0] - mn0); sum0 += s[nt][0];
            s[nt][1] = __expf(s[nt][1] - mn0); sum0 += s[nt][1];
            s[nt][2] = __expf(s[nt][2] - mn1); sum1 += s[nt][2];
            s[nt][3] = __expf(s[nt][3] - mn1); sum1 += s[nt][3];
        }
        sum0 += __shfl_xor_sync(0xffffffffu, sum0, 1);
        sum0 += __shfl_xor_sync(0xffffffffu, sum0, 2);
        sum1 += __shfl_xor_sync(0xffffffffu, sum1, 1);
        sum1 += __shfl_xor_sync(0xffffffffu, sum1, 2);
        l0 = l0 * cr0 + sum0;  l1 = l1 * cr1 + sum1;
        m0 = mn0;              m1 = mn1;
#pragma unroll
        for (int dt = 0; dt < 8; dt++) {
            o[dt][0] *= cr0; o[dt][1] *= cr0;
            o[dt][2] *= cr1; o[dt][3] *= cr1;
        }

        // ---- pack P into A fragments (register-only, hi/lo) ----
        uint32_t ph[4][4], pl[4][4];
#pragma unroll
        for (int ks = 0; ks < 4; ks++) {
            split_pair(s[2*ks  ][0], s[2*ks  ][1], ph[ks][0], pl[ks][0]);
            split_pair(s[2*ks  ][2], s[2*ks  ][3], ph[ks][1], pl[ks][1]);
            split_pair(s[2*ks+1][0], s[2*ks+1][1], ph[ks][2], pl[ks][2]);
            split_pair(s[2*ks+1][2], s[2*ks+1][3], ph[ks][3], pl[ks][3]);
        }

        // ---- O += P V (3-pass, V fragments via ldmatrix.trans) ----
        {
            const int vcolb = (lane >> 4) * 16;
#pragma unroll
            for (int ks = 0; ks < 4; ks++) {
                const int vrow = ks * 16 + (lane & 15);
                uint32_t vh4[4][4], vl4[4][4];
#pragma unroll
                for (int np = 0; np < 4; np++) {
                    ldsm_x4_t(vh4[np], vH + vrow * FROWB + np * 32 + vcolb);
                    ldsm_x4_t(vl4[np], vL + vrow * FROWB + np * 32 + vcolb);
                }
#pragma unroll
                for (int dt = 0; dt < 8; dt++) {
                    uint32_t b0h = vh4[dt >> 1][(dt & 1) * 2];
                    uint32_t b1h = vh4[dt >> 1][(dt & 1) * 2 + 1];
                    uint32_t b0l = vl4[dt >> 1][(dt & 1) * 2];
                    uint32_t b1l = vl4[dt >> 1][(dt & 1) * 2 + 1];
                    mma_bf16(o[dt], ph[ks], b0h, b1h);
                    mma_bf16(o[dt], ph[ks], b0l, b1l);
                    mma_bf16(o[dt], pl[ks], b0h, b1h);
                }
            }
        }
        __syncthreads();
    }

    // ---- epilogue: O * SCALE / l, split hi/lo, write [b][n][h*64+d] ----
    const float inv0 = ATT_SCALE / l0, inv1 = ATT_SCALE / l1;
    const int qrow0 = qt * 64 + 16 * w + (lane >> 2);
    const size_t roff0 = ((size_t)bb * SEQ + qrow0) * EMB + h * HDIM;
    const size_t roff1 = roff0 + (size_t)8 * EMB;
#pragma unroll
    for (int dt = 0; dt < 8; dt++) {
        const int d = dt * 8 + 2 * (lane & 3);
        uint32_t hp, lp;
        split_pair(o[dt][0] * inv0, o[dt][1] * inv0, hp, lp);
        *reinterpret_cast<uint32_t*>(&g_ah[roff0 + d]) = hp;
        *reinterpret_cast<uint32_t*>(&g_al[roff0 + d]) = lp;
        split_pair(o[dt][2] * inv1, o[dt][3] * inv1, hp, lp);
        *reinterpret_cast<uint32_t*>(&g_ah[roff1 + d]) = hp;
        *reinterpret_cast<uint32_t*>(&g_al[roff1 + d]) = lp;
    }
}

// ---------------------------------------------------------------------------
extern "C" void kernel_launch(void* const* d_in, const int* in_sizes, int n_in,
                              void* d_out, int out_size)
{
    const float* x      = (const float*)d_in[0];
    const float* w_qkv  = (const float*)d_in[1];
    const float* b_qkv  = (const float*)d_in[2];
    const float* w_proj = (const float*)d_in[3];
    const float* b_proj = (const float*)d_in[4];
    float* out = (float*)d_out;
    (void)in_sizes; (void)n_in; (void)out_size;

    cudaFuncSetAttribute(mma_gemm_kernel,
                         cudaFuncAttributeMaxDynamicSharedMemorySize, GEMM_SMEM);
    cudaFuncSetAttribute(flash_kernel,
                         cudaFuncAttributeMaxDynamicSharedMemorySize, FLASH_SMEM);

    __nv_bfloat16 *xh, *xl, *wqh, *wql, *wph, *wpl, *ah, *al;
    cudaGetSymbolAddress((void**)&xh,  g_xh);
    cudaGetSymbolAddress((void**)&xl,  g_xl);
    cudaGetSymbolAddress((void**)&wqh, g_wqh);
    cudaGetSymbolAddress((void**)&wql, g_wql);
    cudaGetSymbolAddress((void**)&wph, g_wph);
    cudaGetSymbolAddress((void**)&wpl, g_wpl);
    cudaGetSymbolAddress((void**)&ah,  g_ah);
    cudaGetSymbolAddress((void**)&al,  g_al);

    // 1) split inputs to bf16 hi/lo
    convert_split_kernel<<<(MTOT * EMB + 255) / 256, 256>>>(x, xh, xl, MTOT * EMB);
    transpose_split_kernel<<<dim3(3 * EMB / 32, EMB / 32), dim3(32, 8)>>>(w_qkv, 3 * EMB, wqh, wql);
    transpose_split_kernel<<<dim3(EMB / 32, EMB / 32), dim3(32, 8)>>>(w_proj, EMB, wph, wpl);
    // 2) QKV GEMM (HMMA bf16x3) -> q/k/v bf16 hi/lo
    mma_gemm_kernel<<<dim3(3 * EMB / 128, MTOT / 128), 512, GEMM_SMEM>>>(
        xh, xl, wqh, wql, b_qkv, nullptr, 0);
    // 3) flash attention (HMMA) -> g_ah/g_al
    flash_kernel<<<dim3(SEQ / 64, BATCH * HEADS), 128, FLASH_SMEM>>>();
    // 4) proj GEMM (HMMA bf16x3) -> d_out
    mma_gemm_kernel<<<dim3(EMB / 128, MTOT / 128), 512, GEMM_SMEM>>>(
        ah, al, wph, wpl, b_proj, out, 1);
}

// round 16
// speedup vs baseline: 1.1109x; 1.1109x over previous
#include <cuda_runtime.h>
#include <cuda_bf16.h>
#include <cstdint>

#define EMB 1024
#define HEADS 16
#define HDIM 64
#define BATCH 2
#define SEQ 2048
#define MTOT (BATCH*SEQ)
#define ATT_SCALE 0.125f

// ---------------------------------------------------------------------------
// Device-global scratch (no allocations allowed)
// ---------------------------------------------------------------------------
#define QKV_ELEMS ((size_t)BATCH*HEADS*SEQ*HDIM)
__device__ __align__(256) __nv_bfloat16 g_xh[(size_t)MTOT*EMB];
__device__ __align__(256) __nv_bfloat16 g_xl[(size_t)MTOT*EMB];
__device__ __align__(256) __nv_bfloat16 g_wqh[(size_t)3*EMB*EMB];
__device__ __align__(256) __nv_bfloat16 g_wql[(size_t)3*EMB*EMB];
__device__ __align__(256) __nv_bfloat16 g_wph[(size_t)EMB*EMB];
__device__ __align__(256) __nv_bfloat16 g_wpl[(size_t)EMB*EMB];
__device__ __align__(256) __nv_bfloat16 g_qh[QKV_ELEMS];
__device__ __align__(256) __nv_bfloat16 g_ql[QKV_ELEMS];
__device__ __align__(256) __nv_bfloat16 g_kh[QKV_ELEMS];
__device__ __align__(256) __nv_bfloat16 g_kl[QKV_ELEMS];
__device__ __align__(256) __nv_bfloat16 g_vh[QKV_ELEMS];
__device__ __align__(256) __nv_bfloat16 g_vl[QKV_ELEMS];
__device__ __align__(256) __nv_bfloat16 g_ah[(size_t)MTOT*EMB];
__device__ __align__(256) __nv_bfloat16 g_al[(size_t)MTOT*EMB];

// ---------------------------------------------------------------------------
// Low-level helpers (all plain sm_80+ PTX — compiles at compute_103)
// ---------------------------------------------------------------------------
__device__ __forceinline__ uint32_t smem_u32(const void* p) {
    uint32_t a;
    asm("{ .reg .u64 t; cvta.to.shared.u64 t, %1; cvt.u32.u64 %0, t; }"
        : "=r"(a) : "l"(p));
    return a;
}
__device__ __forceinline__ void ldsm_x4(uint32_t r[4], uint32_t addr) {
    asm volatile("ldmatrix.sync.aligned.m8n8.x4.shared.b16 {%0,%1,%2,%3}, [%4];"
        : "=r"(r[0]), "=r"(r[1]), "=r"(r[2]), "=r"(r[3]) : "r"(addr));
}
__device__ __forceinline__ void ldsm_x4_t(uint32_t r[4], uint32_t addr) {
    asm volatile("ldmatrix.sync.aligned.m8n8.x4.trans.shared.b16 {%0,%1,%2,%3}, [%4];"
        : "=r"(r[0]), "=r"(r[1]), "=r"(r[2]), "=r"(r[3]) : "r"(addr));
}
__device__ __forceinline__ void mma_bf16(float c[4], const uint32_t a[4],
                                         uint32_t b0, uint32_t b1) {
    asm volatile("mma.sync.aligned.m16n8k16.row.col.f32.bf16.bf16.f32 "
        "{%0,%1,%2,%3}, {%4,%5,%6,%7}, {%8,%9}, {%0,%1,%2,%3};"
        : "+f"(c[0]), "+f"(c[1]), "+f"(c[2]), "+f"(c[3])
        : "r"(a[0]), "r"(a[1]), "r"(a[2]), "r"(a[3]), "r"(b0), "r"(b1));
}
#define CP_ASYNC16(sptr, gptr) \
    asm volatile("cp.async.cg.shared.global [%0], [%1], 16;" \
                 :: "r"(sptr), "l"(gptr) : "memory")
#define CP_COMMIT()  asm volatile("cp.async.commit_group;" ::: "memory")
#define CP_WAIT0()   asm volatile("cp.async.wait_group 0;" ::: "memory")
#define CP_WAIT1()   asm volatile("cp.async.wait_group 1;" ::: "memory")

// XOR swizzle within 1KB (8 rows x 128B): chunk index ^= row%8
#define SWZ(off) ((off) ^ (((off) >> 3) & 0x70))

__device__ __forceinline__ float truncbf(float x) {
    return __uint_as_float(__float_as_uint(x) & 0xffff0000u);
}
// pack two f32 into bf16x2 (lo = e0 in low half)
__device__ __forceinline__ uint32_t pack_bf16x2(float lo, float hi) {
    uint32_t r;
    asm("cvt.rn.satfinite.bf16x2.f32 %0, %1, %2;" : "=r"(r) : "f"(hi), "f"(lo));
    return r;
}
__device__ __forceinline__ void split_pair(float e0, float e1,
                                           uint32_t& hp, uint32_t& lp) {
    float h0 = truncbf(e0), h1 = truncbf(e1);
    hp = pack_bf16x2(h0, h1);
    lp = pack_bf16x2(e0 - h0, e1 - h1);
}

// ---------------------------------------------------------------------------
// Split fp32 -> (hi, lo) bf16
// ---------------------------------------------------------------------------
__global__ void convert_split_kernel(const float* __restrict__ in,
                                     __nv_bfloat16* __restrict__ hi,
                                     __nv_bfloat16* __restrict__ lo, int n)
{
    int i = blockIdx.x * blockDim.x + threadIdx.x;
    if (i < n) {
        float x = in[i];
        float h = truncbf(x);
        hi[i] = __float2bfloat16(h);
        lo[i] = __float2bfloat16(x - h);
    }
}

// ---------------------------------------------------------------------------
// Transpose + split: W[1024][N] fp32 -> WT[N][1024] bf16 hi/lo
// ---------------------------------------------------------------------------
__global__ void transpose_split_kernel(const float* __restrict__ W, int N,
                                       __nv_bfloat16* __restrict__ Th,
                                       __nv_bfloat16* __restrict__ Tl)
{
    __shared__ float tile[32][33];
    int n0 = blockIdx.x * 32, k0 = blockIdx.y * 32;
    int tx = threadIdx.x, ty = threadIdx.y;
#pragma unroll
    for (int i = 0; i < 32; i += 8)
        tile[ty + i][tx] = W[(size_t)(k0 + ty + i) * N + n0 + tx];
    __syncthreads();
#pragma unroll
    for (int i = 0; i < 32; i += 8) {
        float v = tile[tx][ty + i];
        float h = truncbf(v);
        size_t idx = (size_t)(n0 + ty + i) * EMB + k0 + tx;
        Th[idx] = __float2bfloat16(h);
        Tl[idx] = __float2bfloat16(v - h);
    }
}

// ---------------------------------------------------------------------------
// HMMA bf16x3 GEMM: C[4096][Ntot] = A[4096][1024] @ B^T  (B stored [N][1024])
// R14: CTA tile 128x64, 256 threads (8 warps = 4M x 2N, warp tile 32x32),
// 2 CTAs PER SM (launch_bounds(256,2); 96KB smem/CTA) so one CTA's MMA phase
// fills the other's barrier/cp.async bubbles — the structural feature that
// makes the flash kernel 3x more efficient per FLOP. R13's in-warp fragment
// double-buffer reverted (neutral). K-chunk 64, 128B swizzled rows.
// mode 0: QKV epilogue (bias + de-interleave + bf16 hi/lo scatter)
// mode 1: bias + fp32 write to outp.
// ---------------------------------------------------------------------------
#define GKC 64
#define GNCH (EMB/GKC)          // 16
#define GROWB 128               // 64 bf16 = 128B per row, swizzled
#define GA_BYTES (128*GROWB)    // 16384 (one A array: 128 rows)
#define GB_BYTES (64*GROWB)     // 8192  (one B array: 64 rows)
#define GSTAGE (2*GA_BYTES + 2*GB_BYTES)  // 49152
#define GEMM_SMEM (2*GSTAGE)    // 98304

__device__ __forceinline__ void qkv_scatter(int r, int c, float val,
                                            const float* __restrict__ bias)
{
    val += bias[c];
    int bb = r >> 11;
    int n  = r & (SEQ - 1);
    int h   = c / 192;
    int rem = c - h * 192;
    int d   = rem / 3;
    int w   = rem - d * 3;
    size_t idx = (((size_t)(bb * HEADS + h)) * SEQ + n) * HDIM + d;
    float hi = truncbf(val);
    float lo = val - hi;
    __nv_bfloat16* dh = (w == 0) ? g_qh : (w == 1) ? g_kh : g_vh;
    __nv_bfloat16* dl = (w == 0) ? g_ql : (w == 1) ? g_kl : g_vl;
    dh[idx] = __float2bfloat16(hi);
    dl[idx] = __float2bfloat16(lo);
}

__global__ __launch_bounds__(256, 2)
void mma_gemm_kernel(const __nv_bfloat16* __restrict__ Ah,
                     const __nv_bfloat16* __restrict__ Al,
                     const __nv_bfloat16* __restrict__ Bh,
                     const __nv_bfloat16* __restrict__ Bl,
                     const float* __restrict__ bias,
                     float* __restrict__ outp, int mode)
{
    extern __shared__ char smem[];
    const uint32_t sbase = smem_u32(smem);
    const int tid = threadIdx.x, lane = tid & 31, wid = tid >> 5;
    const int wm = (wid >> 1) * 32, wn = (wid & 1) * 32;
    const int mBase = blockIdx.y * 128, nBase = blockIdx.x * 64;

    const int arow = wm + (lane & 15);
    const int acolb = (lane >> 4) * 16;
    const int brow = wn + ((lane >> 4) << 3) + (lane & 7);
    const int bcolb = ((lane >> 3) & 1) * 16;

    float acc[2][4][4];
#pragma unroll
    for (int a = 0; a < 2; a++)
#pragma unroll
        for (int b = 0; b < 4; b++)
#pragma unroll
            for (int e = 0; e < 4; e++) acc[a][b][e] = 0.f;

    // stage loader: A 2x128 rows + B 2x64 rows, 8 x 16B chunks per row
    //   = 3072 tasks / 256 threads = 12 iterations; each i stays in one array.
    auto load_stage = [&](int t, int st) {
        const int k0 = t * GKC;
        const uint32_t sb = sbase + st * GSTAGE;
#pragma unroll
        for (int i = 0; i < 12; i++) {
            int task = i * 256 + tid;
            const __nv_bfloat16* g;
            uint32_t abase;
            int rb, row, ch;
            if (task < 1024)      { g = Ah; abase = 0;     rb = mBase; row = task >> 3;          ch = task & 7; }
            else if (task < 2048) { g = Al; abase = 16384; rb = mBase; row = (task - 1024) >> 3; ch = task & 7; }
            else if (task < 2560) { g = Bh; abase = 32768; rb = nBase; row = (task - 2048) >> 3; ch = task & 7; }
            else                  { g = Bl; abase = 40960; rb = nBase; row = (task - 2560) >> 3; ch = task & 7; }
            const void* gp = g + (size_t)(rb + row) * EMB + k0 + ch * 8;
            CP_ASYNC16(sb + abase + SWZ(row * GROWB + ch * 16), gp);
        }
    };

    load_stage(0, 0); CP_COMMIT();

    for (int t = 0; t < GNCH; t++) {
        const int st = t & 1;
        if (t + 1 < GNCH) { load_stage(t + 1, st ^ 1); CP_COMMIT(); CP_WAIT1(); }
        else              { CP_WAIT0(); }
        __syncthreads();

        const uint32_t aH = sbase + st * GSTAGE;
        const uint32_t aL = aH + 16384, bH = aH + 32768, bL = aH + 40960;
#pragma unroll
        for (int ks = 0; ks < 4; ks++) {
            uint32_t ah4[2][4], al4[2][4], bh4[2][4], bl4[2][4];
            const int acol = ks * 32 + acolb;
#pragma unroll
            for (int mt = 0; mt < 2; mt++) {
                ldsm_x4(ah4[mt], aH + SWZ((arow + mt * 16) * GROWB + acol));
                ldsm_x4(al4[mt], aL + SWZ((arow + mt * 16) * GROWB + acol));
            }
            const int bcol = ks * 32 + bcolb;
#pragma unroll
            for (int np = 0; np < 2; np++) {
                ldsm_x4(bh4[np], bH + SWZ((brow + np * 16) * GROWB + bcol));
                ldsm_x4(bl4[np], bL + SWZ((brow + np * 16) * GROWB + bcol));
            }
#pragma unroll
            for (int mt = 0; mt < 2; mt++)
#pragma unroll
                for (int nt = 0; nt < 4; nt++) {
                    uint32_t b0h = bh4[nt >> 1][(nt & 1) * 2];
                    uint32_t b1h = bh4[nt >> 1][(nt & 1) * 2 + 1];
                    uint32_t b0l = bl4[nt >> 1][(nt & 1) * 2];
                    uint32_t b1l = bl4[nt >> 1][(nt & 1) * 2 + 1];
                    mma_bf16(acc[mt][nt], ah4[mt], b0h, b1h);
                    mma_bf16(acc[mt][nt], ah4[mt], b0l, b1l);
                    mma_bf16(acc[mt][nt], al4[mt], b0h, b1h);
                }
        }
        __syncthreads();
    }

    // epilogue
#pragma unroll
    for (int mt = 0; mt < 2; mt++) {
        const int r0 = mBase + wm + mt * 16 + (lane >> 2);
#pragma unroll
        for (int nt = 0; nt < 4; nt++) {
            const int c0 = nBase + wn + nt * 8 + 2 * (lane & 3);
            if (mode == 0) {
                qkv_scatter(r0,     c0,     acc[mt][nt][0], bias);
                qkv_scatter(r0,     c0 + 1, acc[mt][nt][1], bias);
                qkv_scatter(r0 + 8, c0,     acc[mt][nt][2], bias);
                qkv_scatter(r0 + 8, c0 + 1, acc[mt][nt][3], bias);
            } else {
                float2 v0 = {acc[mt][nt][0] + bias[c0], acc[mt][nt][1] + bias[c0 + 1]};
                float2 v1 = {acc[mt][nt][2] + bias[c0], acc[mt][nt][3] + bias[c0 + 1]};
                *(float2*)(outp + (size_t)r0 * EMB + c0) = v0;
                *(float2*)(outp + (size_t)(r0 + 8) * EMB + c0) = v1;
            }
        }
    }
}

// ---------------------------------------------------------------------------
// Flash attention on HMMA bf16 hi/lo (unchanged). Block = 64 q-rows of one
// (b,h), 4 warps, 64-key tiles, double-buffered K/V cp.async, 2 CTAs/SM.
// S = Qh.Kh + Qh.Kl + Ql.Kh; online softmax in regs; P repacked register-only;
// O += Ph.Vh + Ph.Vl + Pl.Vh (V via ldmatrix.trans). softmax THEN scale.
// Output -> g_ah/g_al bf16 hi/lo at [b][n][h*64+d].
// ---------------------------------------------------------------------------
#define FROWB 144                       // 64 bf16 = 128B data + 16B pad
#define FARR (64*FROWB)                 // 9216
#define FKV_BASE (2*FARR)               // after Qh,Ql
#define FSTAGE (4*FARR)                 // Kh,Kl,Vh,Vl
#define FLASH_SMEM (FKV_BASE + 2*FSTAGE) // 92160

__global__ __launch_bounds__(128, 2)
void flash_kernel()
{
    extern __shared__ char smem[];
    const uint32_t sbase = smem_u32(smem);
    const int tid = threadIdx.x, lane = tid & 31, w = tid >> 5;
    const int bh = blockIdx.y, qt = blockIdx.x;
    const int bb = bh >> 4, h = bh & 15;
    const size_t hoff = (size_t)bh * SEQ * HDIM;

    // --- load Q tile (hi/lo): 2 arrays x 64 rows x 8 chunks = 1024 tasks ---
    {
        const __nv_bfloat16* qa[2] = {g_qh + hoff, g_ql + hoff};
#pragma unroll
        for (int i = 0; i < 8; i++) {
            int task = i * 128 + tid;
            int arr = task >> 9, rem = task & 511;
            int row = rem >> 3, ch = rem & 7;
            const void* gp = qa[arr] + (size_t)(qt * 64 + row) * HDIM + ch * 8;
            CP_ASYNC16(sbase + arr * FARR + row * FROWB + ch * 16, gp);
        }
    }
    CP_COMMIT();

    // 4 arrays x 64 rows x 8 chunks = 2048 tasks
    auto load_kv = [&](int kt, int st) {
        const __nv_bfloat16* ka[4] = {g_kh + hoff, g_kl + hoff,
                                      g_vh + hoff, g_vl + hoff};
        const uint32_t kb = sbase + FKV_BASE + st * FSTAGE;
#pragma unroll
        for (int i = 0; i < 16; i++) {
            int task = i * 128 + tid;
            int arr = task >> 9, rem = task & 511;
            int row = rem >> 3, ch = rem & 7;
            const void* gp = ka[arr] + (size_t)(kt * 64 + row) * HDIM + ch * 8;
            CP_ASYNC16(kb + arr * FARR + row * FROWB + ch * 16, gp);
        }
    };

    load_kv(0, 0); CP_COMMIT();
    CP_WAIT1();               // Q group done
    __syncthreads();

    // --- Q fragments (persistent): 4 k-steps x 4 regs, hi & lo ---
    uint32_t aqh[4][4], aql[4][4];
    {
        const int arow = 16 * w + (lane & 15);
        const int acolb = (lane >> 4) * 16;
#pragma unroll
        for (int ks = 0; ks < 4; ks++) {
            ldsm_x4(aqh[ks], sbase + arow * FROWB + ks * 32 + acolb);
            ldsm_x4(aql[ks], sbase + FARR + arow * FROWB + ks * 32 + acolb);
        }
    }

    float o[8][4];
#pragma unroll
    for (int dt = 0; dt < 8; dt++)
#pragma unroll
        for (int e = 0; e < 4; e++) o[dt][e] = 0.f;
    float m0 = -1e30f, m1 = -1e30f, l0 = 0.f, l1 = 0.f;

    for (int kt = 0; kt < SEQ / 64; kt++) {
        const int st = kt & 1;
        if (kt + 1 < SEQ / 64) { load_kv(kt + 1, st ^ 1); CP_COMMIT(); CP_WAIT1(); }
        else                   { CP_WAIT0(); }
        __syncthreads();

        const uint32_t kH = sbase + FKV_BASE + st * FSTAGE;
        const uint32_t kL = kH + FARR, vH = kH + 2 * FARR, vL = kH + 3 * FARR;

        // ---- S = Q K^T (3-pass) ----
        float s[8][4];
#pragma unroll
        for (int nt = 0; nt < 8; nt++)
#pragma unroll
            for (int e = 0; e < 4; e++) s[nt][e] = 0.f;

        {
            const int brow = ((lane >> 4) << 3) + (lane & 7);
            const int bcolb = ((lane >> 3) & 1) * 16;
#pragma unroll
            for (int ks = 0; ks < 4; ks++) {
                uint32_t bh4[4][4], bl4[4][4];
#pragma unroll
                for (int np = 0; np < 4; np++) {
                    ldsm_x4(bh4[np], kH + (np * 16 + brow) * FROWB + ks * 32 + bcolb);
                    ldsm_x4(bl4[np], kL + (np * 16 + brow) * FROWB + ks * 32 + bcolb);
                }
#pragma unroll
                for (int nt = 0; nt < 8; nt++) {
                    uint32_t b0h = bh4[nt >> 1][(nt & 1) * 2];
                    uint32_t b1h = bh4[nt >> 1][(nt & 1) * 2 + 1];
                    uint32_t b0l = bl4[nt >> 1][(nt & 1) * 2];
                    uint32_t b1l = bl4[nt >> 1][(nt & 1) * 2 + 1];
                    mma_bf16(s[nt], aqh[ks], b0h, b1h);
                    mma_bf16(s[nt], aqh[ks], b0l, b1l);
                    mma_bf16(s[nt], aql[ks], b0h, b1h);
                }
            }
        }

        // ---- online softmax (rows m=lane/4 and m+8; reduce over lane%4) ----
        float vx0 = -1e30f, vx1 = -1e30f;
#pragma unroll
        for (int nt = 0; nt < 8; nt++) {
            vx0 = fmaxf(vx0, fmaxf(s[nt][0], s[nt][1]));
            vx1 = fmaxf(vx1, fmaxf(s[nt][2], s[nt][3]));
        }
        vx0 = fmaxf(vx0, __shfl_xor_sync(0xffffffffu, vx0, 1));
        vx0 = fmaxf(vx0, __shfl_xor_sync(0xffffffffu, vx0, 2));
        vx1 = fmaxf(vx1, __shfl_xor_sync(0xffffffffu, vx1, 1));
        vx1 = fmaxf(vx1, __shfl_xor_sync(0xffffffffu, vx1, 2));
        const float mn0 = fmaxf(m0, vx0), mn1 = fmaxf(m1, vx1);
        const float cr0 = __expf(m0 - mn0), cr1 = __expf(m1 - mn1);
        float sum0 = 0.f, sum1 = 0.f;
#pragma unroll
        for (int nt = 0; nt < 8; nt++) {
            s[nt][0] = __expf(s[nt][0] - mn0); sum0 += s[nt][0];
            s[nt][1] = __expf(s[nt][1] - mn0); sum0 += s[nt][1];
            s[nt][2] = __expf(s[nt][2] - mn1); sum1 += s[nt][2];
            s[nt][3] = __expf(s[nt][3] - mn1); sum1 += s[nt][3];
        }
        sum0 += __shfl_xor_sync(0xffffffffu, sum0, 1);
        sum0 += __shfl_xor_sync(0xffffffffu, sum0, 2);
        sum1 += __shfl_xor_sync(0xffffffffu, sum1, 1);
        sum1 += __shfl_xor_sync(0xffffffffu, sum1, 2);
        l0 = l0 * cr0 + sum0;  l1 = l1 * cr1 + sum1;
        m0 = mn0;              m1 = mn1;
#pragma unroll
        for (int dt = 0; dt < 8; dt++) {
            o[dt][0] *= cr0; o[dt][1] *= cr0;
            o[dt][2] *= cr1; o[dt][3] *= cr1;
        }

        // ---- pack P into A fragments (register-only, hi/lo) ----
        uint32_t ph[4][4], pl[4][4];
#pragma unroll
        for (int ks = 0; ks < 4; ks++) {
            split_pair(s[2*ks  ][0], s[2*ks  ][1], ph[ks][0], pl[ks][0]);
            split_pair(s[2*ks  ][2], s[2*ks  ][3], ph[ks][1], pl[ks][1]);
            split_pair(s[2*ks+1][0], s[2*ks+1][1], ph[ks][2], pl[ks][2]);
            split_pair(s[2*ks+1][2], s[2*ks+1][3], ph[ks][3], pl[ks][3]);
        }

        // ---- O += P V (3-pass, V fragments via ldmatrix.trans) ----
        {
            const int vcolb = (lane >> 4) * 16;
#pragma unroll
            for (int ks = 0; ks < 4; ks++) {
                const int vrow = ks * 16 + (lane & 15);
                uint32_t vh4[4][4], vl4[4][4];
#pragma unroll
                for (int np = 0; np < 4; np++) {
                    ldsm_x4_t(vh4[np], vH + vrow * FROWB + np * 32 + vcolb);
                    ldsm_x4_t(vl4[np], vL + vrow * FROWB + np * 32 + vcolb);
                }
#pragma unroll
                for (int dt = 0; dt < 8; dt++) {
                    uint32_t b0h = vh4[dt >> 1][(dt & 1) * 2];
                    uint32_t b1h = vh4[dt >> 1][(dt & 1) * 2 + 1];
                    uint32_t b0l = vl4[dt >> 1][(dt & 1) * 2];
                    uint32_t b1l = vl4[dt >> 1][(dt & 1) * 2 + 1];
                    mma_bf16(o[dt], ph[ks], b0h, b1h);
                    mma_bf16(o[dt], ph[ks], b0l, b1l);
                    mma_bf16(o[dt], pl[ks], b0h, b1h);
                }
            }
        }
        __syncthreads();
    }

    // ---- epilogue: O * SCALE / l, split hi/lo, write [b][n][h*64+d] ----
    const float inv0 = ATT_SCALE / l0, inv1 = ATT_SCALE / l1;
    const int qrow0 = qt * 64 + 16 * w + (lane >> 2);
    const size_t roff0 = ((size_t)bb * SEQ + qrow0) * EMB + h * HDIM;
    const size_t roff1 = roff0 + (size_t)8 * EMB;
#pragma unroll
    for (int dt = 0; dt < 8; dt++) {
        const int d = dt * 8 + 2 * (lane & 3);
        uint32_t hp, lp;
        split_pair(o[dt][0] * inv0, o[dt][1] * inv0, hp, lp);
        *reinterpret_cast<uint32_t*>(&g_ah[roff0 + d]) = hp;
        *reinterpret_cast<uint32_t*>(&g_al[roff0 + d]) = lp;
        split_pair(o[dt][2] * inv1, o[dt][3] * inv1, hp, lp);
        *reinterpret_cast<uint32_t*>(&g_ah[roff1 + d]) = hp;
        *reinterpret_cast<uint32_t*>(&g_al[roff1 + d]) = lp;
    }
}

// ---------------------------------------------------------------------------
extern "C" void kernel_launch(void* const* d_in, const int* in_sizes, int n_in,
                              void* d_out, int out_size)
{
    const float* x      = (const float*)d_in[0];
    const float* w_qkv  = (const float*)d_in[1];
    const float* b_qkv  = (const float*)d_in[2];
    const float* w_proj = (const float*)d_in[3];
    const float* b_proj = (const float*)d_in[4];
    float* out = (float*)d_out;
    (void)in_sizes; (void)n_in; (void)out_size;

    cudaFuncSetAttribute(mma_gemm_kernel,
                         cudaFuncAttributeMaxDynamicSharedMemorySize, GEMM_SMEM);
    cudaFuncSetAttribute(flash_kernel,
                         cudaFuncAttributeMaxDynamicSharedMemorySize, FLASH_SMEM);

    __nv_bfloat16 *xh, *xl, *wqh, *wql, *wph, *wpl, *ah, *al;
    cudaGetSymbolAddress((void**)&xh,  g_xh);
    cudaGetSymbolAddress((void**)&xl,  g_xl);
    cudaGetSymbolAddress((void**)&wqh, g_wqh);
    cudaGetSymbolAddress((void**)&wql, g_wql);
    cudaGetSymbolAddress((void**)&wph, g_wph);
    cudaGetSymbolAddress((void**)&wpl, g_wpl);
    cudaGetSymbolAddress((void**)&ah,  g_ah);
    cudaGetSymbolAddress((void**)&al,  g_al);

    // 1) split inputs to bf16 hi/lo
    convert_split_kernel<<<(MTOT * EMB + 255) / 256, 256>>>(x, xh, xl, MTOT * EMB);
    transpose_split_kernel<<<dim3(3 * EMB / 32, EMB / 32), dim3(32, 8)>>>(w_qkv, 3 * EMB, wqh, wql);
    transpose_split_kernel<<<dim3(EMB / 32, EMB / 32), dim3(32, 8)>>>(w_proj, EMB, wph, wpl);
    // 2) QKV GEMM (HMMA bf16x3) -> q/k/v bf16 hi/lo
    mma_gemm_kernel<<<dim3(3 * EMB / 64, MTOT / 128), 256, GEMM_SMEM>>>(
        xh, xl, wqh, wql, b_qkv, nullptr, 0);
    // 3) flash attention (HMMA) -> g_ah/g_al
    flash_kernel<<<dim3(SEQ / 64, BATCH * HEADS), 128, FLASH_SMEM>>>();
    // 4) proj GEMM (HMMA bf16x3) -> d_out
    mma_gemm_kernel<<<dim3(EMB / 64, MTOT / 128), 256, GEMM_SMEM>>>(
        ah, al, wph, wpl, b_proj, out, 1);
}